// round 10
// baseline (speedup 1.0000x reference)
#include <cuda_runtime.h>

// Problem constants
#define CCH     12            // path channels: 1 time + 3 orig + 8 aug
#define TT      1024
#define NCHUNK  16
#define CHLEN   64            // chunk 15 has 63 steps (16*64-1 = 1023)
#define NPATH   64            // B(32) * GROUPS(2)
#define NBATCH  32
#define SIGC    1884          // 12 + 144 + 1728
#define L2OFF   12
#define L3OFF   156
#define TSTRIDE 68            // padded t-stride of transposed dx (float4-aligned)
#define SIGQ    471           // SIGC / 4 float4s

// Scratch (no cudaMalloc allowed)
__device__ __align__(16) float g_part[NPATH * NCHUNK * SIGC]; // ~7.7 MB
__device__ __align__(16) float g_sig [NPATH * SIGC];          // ~0.5 MB
__device__ int g_path_cnt [NPATH];    // zero-init; self-resetting
__device__ int g_batch_cnt[NBATCH];   // zero-init; self-resetting

// ---------------------------------------------------------------------------
// Single fused kernel. grid = (NCHUNK, NPATH) = 1024 blocks, block = 160.
// Phase 1 (all blocks): partial signature of one 64-step chunk (FFMA2 path).
// Phase 2 (last block per path): Chen-fold the path's 16 partials -> g_sig.
// Phase 3 (last path per batch): 32-output GEMV + sigmoid -> out.
// Counters use the standard threadfence + atomicAdd release/acquire pattern
// and reset themselves, so every graph replay starts from a clean state.
// ---------------------------------------------------------------------------
__global__ __launch_bounds__(160) void sig_fused_kernel(
        const float* __restrict__ x,
        const float* __restrict__ aug_w,
        const float* __restrict__ lin_w,
        const float* __restrict__ lin_b,
        float* __restrict__ out)
{
    __shared__ __align__(16) float dxsh[CHLEN * CCH];       // [t][c], 3 KB
    __shared__ __align__(16) float dxT [CCH * TSTRIDE];     // [c][t_padded]
    __shared__ float xsh[(CHLEN + 1) * 3];
    __shared__ float awsh[8 * 3];
    __shared__ int   sh_last;

    const int tid   = threadIdx.x;
    const int chunk = blockIdx.x;
    const int p     = blockIdx.y;        // path id = b*2 + g
    const int b     = p >> 1;
    const int g     = p & 1;
    const int t0    = chunk * CHLEN;
    const int ns    = (chunk == NCHUNK - 1) ? (CHLEN - 1) : CHLEN;   // steps

    // ------------------------- Phase 1: chunk partial -------------------------
    for (int idx = tid; idx < (ns + 1) * 3; idx += blockDim.x)
        xsh[idx] = x[(b * TT + t0) * 3 + idx];
    if (tid < 24) awsh[tid] = aug_w[g * 24 + tid];
    __syncthreads();

    for (int idx = tid; idx < ns * CCH; idx += blockDim.x) {
        int t = idx / CCH, c = idx - t * CCH;
        float xd0 = xsh[(t + 1) * 3 + 0] - xsh[t * 3 + 0];
        float xd1 = xsh[(t + 1) * 3 + 1] - xsh[t * 3 + 1];
        float xd2 = xsh[(t + 1) * 3 + 2] - xsh[t * 3 + 2];
        float v;
        if (c == 0)      v = 1.0f / 1023.0f;
        else if (c == 1) v = xd0;
        else if (c == 2) v = xd1;
        else if (c == 3) v = xd2;
        else {
            int e = c - 4;
            v = fmaf(awsh[e * 3 + 0], xd0,
                fmaf(awsh[e * 3 + 1], xd1,
                     awsh[e * 3 + 2] * xd2));
        }
        dxsh[idx] = v;
        dxT[c * TSTRIDE + t] = v;
    }
    __syncthreads();

    if (tid < 144) {
        const int i = tid / CCH, j = tid - CCH * (tid / CCH);
        unsigned long long S3p[6];
#pragma unroll
        for (int k = 0; k < 6; k++) S3p[k] = 0ULL;
        float S2 = 0.0f;
        float s1 = 0.0f;
        const unsigned long long* __restrict__ dx64 =
            (const unsigned long long*)dxsh;                 // 6 u64 per row
        const float4* __restrict__ diT = (const float4*)(dxT + i * TSTRIDE);
        const float4* __restrict__ djT = (const float4*)(dxT + j * TSTRIDE);

#define SIG_STEP(tq, di_, dj_) {                                              \
        const unsigned long long* dp = dx64 + (size_t)(tq) * 6;               \
        const ulonglong2 v0 = *(const ulonglong2*)(dp);                       \
        const ulonglong2 v1 = *(const ulonglong2*)(dp + 2);                   \
        const ulonglong2 v2 = *(const ulonglong2*)(dp + 4);                   \
        const float cc = fmaf(fmaf((di_), 1.0f/6.0f, 0.5f * s1), (dj_), S2);  \
        unsigned long long ccp;                                               \
        asm("mov.b64 %0, {%1, %1};" : "=l"(ccp) : "f"(cc));                   \
        asm("fma.rn.f32x2 %0, %1, %2, %0;" : "+l"(S3p[0]) : "l"(ccp), "l"(v0.x)); \
        asm("fma.rn.f32x2 %0, %1, %2, %0;" : "+l"(S3p[1]) : "l"(ccp), "l"(v0.y)); \
        asm("fma.rn.f32x2 %0, %1, %2, %0;" : "+l"(S3p[2]) : "l"(ccp), "l"(v1.x)); \
        asm("fma.rn.f32x2 %0, %1, %2, %0;" : "+l"(S3p[3]) : "l"(ccp), "l"(v1.y)); \
        asm("fma.rn.f32x2 %0, %1, %2, %0;" : "+l"(S3p[4]) : "l"(ccp), "l"(v2.x)); \
        asm("fma.rn.f32x2 %0, %1, %2, %0;" : "+l"(S3p[5]) : "l"(ccp), "l"(v2.y)); \
        S2 = fmaf(fmaf((di_), 0.5f, s1), (dj_), S2);                          \
        s1 += (di_); }

        const int nq = ns >> 2;           // full quads of steps
#pragma unroll 4
        for (int tb = 0; tb < nq; tb++) {
            const float4 di4 = diT[tb];
            const float4 dj4 = djT[tb];
            SIG_STEP(tb * 4 + 0, di4.x, dj4.x);
            SIG_STEP(tb * 4 + 1, di4.y, dj4.y);
            SIG_STEP(tb * 4 + 2, di4.z, dj4.z);
            SIG_STEP(tb * 4 + 3, di4.w, dj4.w);
        }
        for (int t = nq * 4; t < ns; t++) {   // remainder (0 or 3 steps)
            const float di = dxT[i * TSTRIDE + t];
            const float dj = dxT[j * TSTRIDE + t];
            SIG_STEP(t, di, dj);
        }
#undef SIG_STEP

        float* o = &g_part[(size_t)(p * NCHUNK + chunk) * SIGC];
        if (j == 0) o[i] = s1;
        o[L2OFF + tid] = S2;
        ulonglong2* o2 = (ulonglong2*)(o + L3OFF + tid * 12);
        o2[0] = make_ulonglong2(S3p[0], S3p[1]);
        o2[1] = make_ulonglong2(S3p[2], S3p[3]);
        o2[2] = make_ulonglong2(S3p[4], S3p[5]);
    }

    // --------------------- Phase 2 gate: last block of path --------------------
    __threadfence();
    __syncthreads();
    if (tid == 0) {
        int old = atomicAdd(&g_path_cnt[p], 1);
        sh_last = (old == NCHUNK - 1);
        if (sh_last) g_path_cnt[p] = 0;     // reset for next replay
    }
    __syncthreads();
    if (!sh_last) return;
    __threadfence();   // acquire: make other blocks' g_part writes visible

    // ------------------- Phase 2: Chen-fold 16 partials -> g_sig ---------------
    if (tid < 144) {
        const int i = tid / CCH, j = tid - CCH * (tid / CCH);
        const float* __restrict__ base = &g_part[(size_t)p * NCHUNK * SIGC];

        float A3[12];
        {
            const float4* p4 = (const float4*)(base + L3OFF + tid * 12);
            float4 v0 = p4[0], v1 = p4[1], v2 = p4[2];
            A3[0] = v0.x; A3[1] = v0.y; A3[2]  = v0.z; A3[3]  = v0.w;
            A3[4] = v1.x; A3[5] = v1.y; A3[6]  = v1.z; A3[7]  = v1.w;
            A3[8] = v2.x; A3[9] = v2.y; A3[10] = v2.z; A3[11] = v2.w;
        }
        float A2ij = base[L2OFF + tid];
        float a1i  = base[i];

#pragma unroll 3
        for (int s = 1; s < NCHUNK; s++) {
            const float* __restrict__ bp = base + (size_t)s * SIGC;
            const float4 u0 = *(const float4*)(bp + 0);
            const float4 u1 = *(const float4*)(bp + 4);
            const float4 u2 = *(const float4*)(bp + 8);
            const float4 q0 = *(const float4*)(bp + L2OFF + j * 12 + 0);
            const float4 q1 = *(const float4*)(bp + L2OFF + j * 12 + 4);
            const float4 q2 = *(const float4*)(bp + L2OFF + j * 12 + 8);
            const float4 r0 = *(const float4*)(bp + L3OFF + tid * 12 + 0);
            const float4 r1 = *(const float4*)(bp + L3OFF + tid * 12 + 4);
            const float4 r2 = *(const float4*)(bp + L3OFF + tid * 12 + 8);
            const float  b2 = bp[L2OFF + i * CCH + j];
            const float b1i = bp[i];
            const float b1j = bp[j];

            // A3[k] += B3 + a1i*B2[j][k] + A2ij*B1[k]   (old A1, old A2)
            A3[0]  += r0.x + fmaf(a1i, q0.x, A2ij * u0.x);
            A3[1]  += r0.y + fmaf(a1i, q0.y, A2ij * u0.y);
            A3[2]  += r0.z + fmaf(a1i, q0.z, A2ij * u0.z);
            A3[3]  += r0.w + fmaf(a1i, q0.w, A2ij * u0.w);
            A3[4]  += r1.x + fmaf(a1i, q1.x, A2ij * u1.x);
            A3[5]  += r1.y + fmaf(a1i, q1.y, A2ij * u1.y);
            A3[6]  += r1.z + fmaf(a1i, q1.z, A2ij * u1.z);
            A3[7]  += r1.w + fmaf(a1i, q1.w, A2ij * u1.w);
            A3[8]  += r2.x + fmaf(a1i, q2.x, A2ij * u2.x);
            A3[9]  += r2.y + fmaf(a1i, q2.y, A2ij * u2.y);
            A3[10] += r2.z + fmaf(a1i, q2.z, A2ij * u2.z);
            A3[11] += r2.w + fmaf(a1i, q2.w, A2ij * u2.w);
            A2ij += b2 + a1i * b1j;
            a1i  += b1i;
        }

        float* so = &g_sig[(size_t)p * SIGC];
        if (j == 0) so[i] = a1i;
        so[L2OFF + tid] = A2ij;
        float4* o4 = (float4*)(so + L3OFF + tid * 12);
        o4[0] = make_float4(A3[0], A3[1], A3[2],  A3[3]);
        o4[1] = make_float4(A3[4], A3[5], A3[6],  A3[7]);
        o4[2] = make_float4(A3[8], A3[9], A3[10], A3[11]);
    }

    // --------------------- Phase 3 gate: last path of batch --------------------
    __threadfence();
    __syncthreads();
    if (tid == 0) {
        int old = atomicAdd(&g_batch_cnt[b], 1);
        sh_last = (old == 1);
        if (sh_last) g_batch_cnt[b] = 0;    // reset for next replay
    }
    __syncthreads();
    if (!sh_last) return;
    __threadfence();   // acquire: other path's g_sig writes visible

    // --------------------- Phase 3: GEMV + sigmoid for batch b -----------------
    {
        const int warp = tid >> 5;          // 0..4
        const int lane = tid & 31;
        const float4* __restrict__ s4 =
            (const float4*)&g_sig[(size_t)(2 * b) * SIGC];  // contiguous pair
        const int NV = (2 * SIGC) / 4;      // 942

        for (int o = warp; o < 32; o += 5) {
            const float4* __restrict__ w4 =
                (const float4*)(lin_w + (size_t)o * 2 * SIGC);
            float ax = 0.0f, ay = 0.0f, az = 0.0f, aw = 0.0f;
            for (int f = lane; f < NV; f += 32) {
                float4 sv = s4[f];
                float4 wv = w4[f];
                ax = fmaf(sv.x, wv.x, ax);
                ay = fmaf(sv.y, wv.y, ay);
                az = fmaf(sv.z, wv.z, az);
                aw = fmaf(sv.w, wv.w, aw);
            }
            float acc = (ax + ay) + (az + aw);
#pragma unroll
            for (int off = 16; off > 0; off >>= 1)
                acc += __shfl_down_sync(0xffffffffu, acc, off);
            if (lane == 0) {
                float z = acc + lin_b[o];
                out[b * 32 + o] = 1.0f / (1.0f + expf(-z));
            }
        }
    }
}

// ---------------------------------------------------------------------------
extern "C" void kernel_launch(void* const* d_in, const int* in_sizes, int n_in,
                              void* d_out, int out_size)
{
    const float* x     = (const float*)d_in[0];  // (32,1024,3)
    const float* aug_w = (const float*)d_in[1];  // (2,8,3)
    // d_in[2] = aug_b : unused (signature is translation-invariant)
    const float* lin_w = (const float*)d_in[3];  // (32, 3768)
    const float* lin_b = (const float*)d_in[4];  // (32,)
    float* out = (float*)d_out;                  // (32,32) float32

    dim3 grid(NCHUNK, NPATH);
    sig_fused_kernel<<<grid, 160>>>(x, aug_w, lin_w, lin_b, out);
}